// round 16
// baseline (speedup 1.0000x reference)
#include <cuda_runtime.h>
#include <cuda_fp16.h>
#include <math.h>
#include <stdint.h>

#define D_MODEL 512
#define D_FF 2048
#define BATCH 2
#define SEQ 2048
#define NHEADS 8
#define EDIM 64
#define ROWS (BATCH*SEQ)
#define BH (BATCH*NHEADS)
#define GELU_CF 0.7978845608028654f
#define WSZ  (2*D_MODEL*D_MODEL)
#define W1SZ (2*D_MODEL*D_FF)

// ---------------- f32 scratch ----------------
__device__ float g_x[ROWS*D_MODEL];
__device__ float g_xb[ROWS*D_MODEL];
__device__ float g_o[ROWS*D_MODEL];
__device__ float g_po0[ROWS*D_MODEL];
__device__ float g_po1[ROWS*D_MODEL];
__device__ float g_l0[BH*SEQ];
__device__ float g_l1[BH*SEQ];

// ---------------- fp16 TRANSPOSED weights ([layer][N][K]) ----------------
__device__ uint16_t s_Wq_h[WSZ];
__device__ uint16_t s_Wk_h[WSZ];
__device__ uint16_t s_Wv_h[WSZ];
__device__ uint16_t s_Wo_h[WSZ];
__device__ uint16_t s_W1_h[W1SZ];
__device__ uint16_t s_W2_h[W1SZ];

// ---------------- fp16 activations ----------------
__device__ uint16_t s_x_h[ROWS*D_MODEL];
__device__ uint16_t s_xb_h[ROWS*D_MODEL];
__device__ uint16_t s_q_h[ROWS*D_MODEL];
__device__ uint16_t s_k_h[ROWS*D_MODEL];
__device__ uint16_t s_vT_h[ROWS*D_MODEL];   // [bh][e][tok]
__device__ uint16_t s_attn_h[ROWS*D_MODEL];
__device__ uint16_t s_h_h[ROWS*D_FF];

// =======================================================================
// helpers
// =======================================================================
__device__ __forceinline__ uint32_t hpack2(float x0, float x1) {
    __half2 hh = __floats2half2_rn(x0, x1);
    return *reinterpret_cast<uint32_t*>(&hh);
}

__device__ __forceinline__ void mma_f16(float* c, const uint32_t* a, const uint32_t* b) {
    asm volatile(
        "mma.sync.aligned.m16n8k16.row.col.f32.f16.f16.f32 "
        "{%0,%1,%2,%3}, {%4,%5,%6,%7}, {%8,%9}, {%0,%1,%2,%3};"
        : "+f"(c[0]), "+f"(c[1]), "+f"(c[2]), "+f"(c[3])
        : "r"(a[0]), "r"(a[1]), "r"(a[2]), "r"(a[3]), "r"(b[0]), "r"(b[1]));
}

__device__ __forceinline__ void ldsm_x4(uint32_t* r, uint32_t addr) {
    asm volatile("ldmatrix.sync.aligned.m8n8.x4.shared.b16 {%0,%1,%2,%3}, [%4];"
        : "=r"(r[0]), "=r"(r[1]), "=r"(r[2]), "=r"(r[3]) : "r"(addr));
}

__device__ __forceinline__ uint32_t smem_u32(const void* p) {
    uint32_t a;
    asm("{ .reg .u64 t; cvta.to.shared.u64 t, %1; cvt.u32.u64 %0, t; }"
        : "=r"(a) : "l"(p));
    return a;
}

__device__ __forceinline__ void cp16(uint32_t dst, const void* src) {
    asm volatile("cp.async.cg.shared.global [%0], [%1], 16;\n" :: "r"(dst), "l"(src));
}
__device__ __forceinline__ void cp_commit() {
    asm volatile("cp.async.commit_group;\n" ::: "memory");
}
__device__ __forceinline__ void cp_wait2() {
    asm volatile("cp.async.wait_group 2;\n" ::: "memory");
}
__device__ __forceinline__ void cp_wait1() {
    asm volatile("cp.async.wait_group 1;\n" ::: "memory");
}
__device__ __forceinline__ void cp_wait0() {
    asm volatile("cp.async.wait_group 0;\n" ::: "memory");
}

// =======================================================================
// prologue: weight transpose (z=0..11) + input split (z=12)
// =======================================================================
__global__ __launch_bounds__(256) void transp_split(
    const float* __restrict__ Wq, const float* __restrict__ Wk,
    const float* __restrict__ Wv, const float* __restrict__ Wo,
    const float* __restrict__ W1, const float* __restrict__ W2,
    const float* __restrict__ x)
{
    if (blockIdx.z == 12) {
        int bid = blockIdx.y * 64 + blockIdx.x;
        if (bid >= ROWS * D_MODEL / 1024) return;
        int idx = (bid * 256 + threadIdx.x) * 4;
        float4 v = *(const float4*)(x + idx);
        *(float4*)(g_x + idx) = v;
        *(uint32_t*)&s_x_h[idx]     = hpack2(v.x, v.y);
        *(uint32_t*)&s_x_h[idx + 2] = hpack2(v.z, v.w);
        return;
    }
    const int w = blockIdx.z >> 1, layer = blockIdx.z & 1;
    const float* src; uint16_t* dh; int K, N;
    switch (w) {
        case 0: src = Wq; dh = s_Wq_h; K = 512;  N = 512;  break;
        case 1: src = Wk; dh = s_Wk_h; K = 512;  N = 512;  break;
        case 2: src = Wv; dh = s_Wv_h; K = 512;  N = 512;  break;
        case 3: src = Wo; dh = s_Wo_h; K = 512;  N = 512;  break;
        case 4: src = W1; dh = s_W1_h; K = 512;  N = 2048; break;
        default: src = W2; dh = s_W2_h; K = 2048; N = 512; break;
    }
    const int k0 = blockIdx.x * 32, n0 = blockIdx.y * 32;
    if (k0 >= K || n0 >= N) return;
    src += (size_t)layer * K * N;
    dh  += (size_t)layer * K * N;

    __shared__ float t[32][33];
    const int tid = threadIdx.x;
    const int tx = tid & 31, ty = tid >> 5;
    #pragma unroll
    for (int i = 0; i < 4; i++) {
        int k = ty + i * 8;
        t[k][tx] = src[(size_t)(k0 + k) * N + n0 + tx];
    }
    __syncthreads();
    const int n = tid >> 3, kq = tid & 7;
    float a0 = t[kq*4+0][n], a1 = t[kq*4+1][n], a2 = t[kq*4+2][n], a3 = t[kq*4+3][n];
    size_t o = (size_t)(n0 + n) * K + k0 + kq * 4;
    *(uint32_t*)&dh[o]     = hpack2(a0, a1);
    *(uint32_t*)&dh[o + 2] = hpack2(a2, a3);
}

// =======================================================================
// GEMM: pure fp16, ldmatrix frags. A [M][K], B (transposed weights) [N][K].
// Block tile 128 x (TN*32). 256 thr. 4-stage cp.async pipeline, single sync.
// =======================================================================
#define A_PITCH 40

// epi: 0 = bias -> fp16 out; 1 = bias + add -> f32 out; 2 = bias + gelu -> fp16 out;
//      3 = bias -> transposed fp16 V out (s_vT_h), requires TN==2 & head-aligned bn
template<int TN>
__device__ __forceinline__ void gemm_body(
    const uint16_t* __restrict__ Ah, const uint16_t* __restrict__ Bh,
    const float* __restrict__ bias, const float* __restrict__ add,
    float* __restrict__ Cf, uint16_t* __restrict__ Ch,
    int N, int K, int epi, int bm, int bn, char* sm)
{
    constexpr int STAGE = 10240 + TN * 2560;
    constexpr int NP = TN / 2;
    const int tid = threadIdx.x;
    const int wid = tid >> 5;
    const int lane = tid & 31;
    const int wm = wid & 1;
    const int wn = wid >> 1;
    const int fr = lane >> 2;
    const int fkc = (lane & 3) * 2;
    const int mi = lane >> 3, ri = lane & 7;
    const uint32_t sb = smem_u32(sm);

    int aoff[4];
    #pragma unroll
    for (int tm = 0; tm < 4; tm++)
        aoff[tm] = ((wm * 64 + tm * 16 + (mi & 1) * 8 + ri) * A_PITCH + (mi >> 1) * 8) * 2;
    int boff[NP];
    #pragma unroll
    for (int p = 0; p < NP; p++)
        boff[p] = ((wn * (TN * 8) + (p * 2 + (mi >> 1)) * 8 + ri) * A_PITCH + (mi & 1) * 8) * 2;

    float acc[4][TN][4];
    #pragma unroll
    for (int tm = 0; tm < 4; tm++)
        #pragma unroll
        for (int tn = 0; tn < TN; tn++)
            #pragma unroll
            for (int i = 0; i < 4; i++) acc[tm][tn][i] = 0.f;

    const int nChunks = K >> 5;

    auto issue = [&](int st, int kt) {
        uint32_t base = sb + st * STAGE;
        #pragma unroll
        for (int t = 0; t < 2 + NP; t++) {
            int idx = tid + t * 256;
            if (idx < 512) {
                int row = idx >> 2, c4 = idx & 3;
                cp16(base + row * 80 + c4 * 16, Ah + (size_t)(bm + row) * K + kt + c4 * 8);
            } else {
                int j = idx - 512;
                int row = j >> 2, c4 = j & 3;
                cp16(base + 10240 + row * 80 + c4 * 16, Bh + (size_t)(bn + row) * K + kt + c4 * 8);
            }
        }
        cp_commit();
    };

    issue(0, 0);
    if (nChunks > 1) issue(1, 32);

    for (int chunk = 0; chunk < nChunks; chunk++) {
        if (chunk + 2 < nChunks) {
            issue((chunk + 2) & 3, (chunk + 2) << 5);
            cp_wait2();
        } else if (chunk + 1 < nChunks) {
            cp_wait1();
        } else {
            cp_wait0();
        }
        __syncthreads();

        const uint32_t stgA = sb + (chunk & 3) * STAGE;
        const uint32_t stgB = stgA + 10240;

        #pragma unroll
        for (int ks = 0; ks < 2; ks++) {
            const int K0b = ks * 32;
            uint32_t ah[4][4];
            #pragma unroll
            for (int tm = 0; tm < 4; tm++)
                ldsm_x4(ah[tm], stgA + aoff[tm] + K0b);
            uint32_t bhf[TN][2];
            #pragma unroll
            for (int p = 0; p < NP; p++) {
                uint32_t r[4];
                ldsm_x4(r, stgB + boff[p] + K0b);
                bhf[p*2][0] = r[0]; bhf[p*2][1] = r[1];
                bhf[p*2+1][0] = r[2]; bhf[p*2+1][1] = r[3];
            }
            #pragma unroll
            for (int tm = 0; tm < 4; tm++)
                #pragma unroll
                for (int tn = 0; tn < TN; tn++)
                    mma_f16(acc[tm][tn], ah[tm], bhf[tn]);
        }
        // no trailing sync: 4-stage ring + write-ahead-2 + skew<=1 is race-free
    }

    if (epi == 3) {
        __syncthreads();
        uint16_t (*stg)[66] = (uint16_t(*)[66])sm;
        #pragma unroll
        for (int tm = 0; tm < 4; tm++) {
            #pragma unroll
            for (int tn = 0; tn < TN; tn++) {
                int lcol = wn * (TN * 8) + tn * 8 + fkc;
                float b0 = bias[bn + lcol], b1 = bias[bn + lcol + 1];
                #pragma unroll
                for (int half = 0; half < 2; half++) {
                    int lrow = wm * 64 + tm * 16 + fr + half * 8;
                    float v0 = acc[tm][tn][half * 2 + 0] + b0;
                    float v1 = acc[tm][tn][half * 2 + 1] + b1;
                    *(uint32_t*)&stg[lrow][lcol] = hpack2(v0, v1);
                }
            }
        }
        __syncthreads();
        const int bh = (bm >> 11) * NHEADS + (bn >> 6);
        const int tok0 = bm & (SEQ - 1);
        #pragma unroll
        for (int i = tid; i < 64 * 64; i += 256) {
            int e = i >> 6, t2 = (i & 63) * 2;
            uint32_t v = (uint32_t)stg[t2][e] | ((uint32_t)stg[t2 + 1][e] << 16);
            *(uint32_t*)&s_vT_h[((size_t)bh * EDIM + e) * SEQ + tok0 + t2] = v;
        }
        return;
    }

    #pragma unroll
    for (int tm = 0; tm < 4; tm++) {
        #pragma unroll
        for (int tn = 0; tn < TN; tn++) {
            int row0 = bm + wm * 64 + tm * 16 + fr;
            int col = bn + wn * (TN * 8) + tn * 8 + fkc;
            float b0 = bias[col], b1 = bias[col + 1];
            #pragma unroll
            for (int half = 0; half < 2; half++) {
                int row = row0 + half * 8;
                float v0 = acc[tm][tn][half * 2 + 0] + b0;
                float v1 = acc[tm][tn][half * 2 + 1] + b1;
                if (epi == 1) {
                    const float* ap = add + (size_t)row * N + col;
                    v0 += ap[0]; v1 += ap[1];
                    *(float2*)(Cf + (size_t)row * N + col) = make_float2(v0, v1);
                } else {
                    if (epi == 2) {
                        float u = v0;
                        v0 = 0.5f * u * (1.0f + tanhf(GELU_CF * (u + 0.044715f * u * u * u)));
                        u = v1;
                        v1 = 0.5f * u * (1.0f + tanhf(GELU_CF * (u + 0.044715f * u * u * u)));
                    }
                    *(uint32_t*)&Ch[(size_t)row * N + col] = hpack2(v0, v1);
                }
            }
        }
    }
}

// TN=2 path: 3 CTAs/SM (validated win)
__global__ __launch_bounds__(256, 3) void gemm_split2(
    const uint16_t* __restrict__ Ah, const uint16_t* __restrict__ Bh,
    const float* __restrict__ bias, const float* __restrict__ add,
    float* __restrict__ Cf, uint16_t* __restrict__ Ch,
    int N, int K, int epi)
{
    extern __shared__ char sm[];
    gemm_body<2>(Ah, Bh, bias, add, Cf, Ch, N, K, epi,
                 blockIdx.y * 128, blockIdx.x * 64, sm);
}

__global__ __launch_bounds__(256, 3) void gemm_qkv(
    const float* __restrict__ bq, const float* __restrict__ bk,
    const float* __restrict__ bv, int lw)
{
    extern __shared__ char sm[];
    const int z = blockIdx.z;
    if (z == 0) {
        gemm_body<2>(s_x_h, s_Wq_h + lw, bq, nullptr, nullptr, s_q_h,
                     D_MODEL, D_MODEL, 0, blockIdx.y * 128, blockIdx.x * 64, sm);
    } else if (z == 1) {
        gemm_body<2>(s_x_h, s_Wk_h + lw, bk, nullptr, nullptr, s_k_h,
                     D_MODEL, D_MODEL, 0, blockIdx.y * 128, blockIdx.x * 64, sm);
    } else {
        gemm_body<2>(s_x_h, s_Wv_h + lw, bv, nullptr, nullptr, nullptr,
                     D_MODEL, D_MODEL, 3, blockIdx.y * 128, blockIdx.x * 64, sm);
    }
}

// =======================================================================
// Flash attention, 2-way split-KV, pure fp16, ldmatrix frags.
// No-max softmax + tensor-core row sums. 4-stage cp.async, single sync/tile.
// =======================================================================
#define KP 72
#define F_STAGE 18432
#define F_SMEM (4*F_STAGE)

__global__ __launch_bounds__(256, 2) void flash_split(
    const float* __restrict__ tau, const float* __restrict__ delta)
{
    extern __shared__ char sm[];
    const uint32_t sb = smem_u32(sm);
    const int tid = threadIdx.x;
    const int wid = tid >> 5;
    const int lane = tid & 31;
    const int fr = lane >> 2;
    const int fkc = (lane & 3) * 2;
    const int mi = lane >> 3, ri = lane & 7;

    const int nLt = gridDim.x >> 1;
    const int lt = nLt - 1 - (blockIdx.x >> 1);
    const int z = blockIdx.x & 1;
    const int bh = blockIdx.y;
    const int b = bh >> 3, h = bh & 7;
    const int qrow0 = lt * 128;
    const int rA = qrow0 + wid * 16 + fr;
    const int rB = rA + 8;

    int koff[4];
    #pragma unroll
    for (int p = 0; p < 4; p++)
        koff[p] = (((p * 2 + (mi >> 1)) * 8 + ri) * KP + (mi & 1) * 8) * 2;

    uint32_t qh[4][4];
    #pragma unroll
    for (int ks = 0; ks < 4; ks++) {
        int e0 = ks * 16 + fkc;
        size_t oA = (size_t)(b * SEQ + rA) * D_MODEL + h * EDIM + e0;
        size_t oB = (size_t)(b * SEQ + rB) * D_MODEL + h * EDIM + e0;
        qh[ks][0] = *(const uint32_t*)&s_q_h[oA];
        qh[ks][1] = *(const uint32_t*)&s_q_h[oB];
        qh[ks][2] = *(const uint32_t*)&s_q_h[oA + 8];
        qh[ks][3] = *(const uint32_t*)&s_q_h[oB + 8];
    }

    float oacc[8][4];
    #pragma unroll
    for (int t = 0; t < 8; t++)
        #pragma unroll
        for (int i = 0; i < 4; i++) oacc[t][i] = 0.f;
    float lacc[4] = {0.f, 0.f, 0.f, 0.f};
    const uint32_t onesB[2] = {0x3C003C00u, 0x3C003C00u};
    const float sct = 0.125f * __ldg(&tau[b]);

    const int stStart = z * (lt + 1);
    const int nTiles = lt + 1;

    auto issue = [&](int stage, int key_base) {
        uint32_t base = sb + stage * F_STAGE;
        int row = tid >> 2, c4 = tid & 3;
        size_t gk = (size_t)(b * SEQ + key_base + row) * D_MODEL + h * EDIM + c4 * 16;
        uint32_t dk = base + row * 144 + c4 * 32;
        cp16(dk, s_k_h + gk);
        cp16(dk + 16, s_k_h + gk + 8);
        size_t gv = ((size_t)bh * EDIM + row) * SEQ + key_base + c4 * 16;
        uint32_t dv = base + 9216 + row * 144 + c4 * 32;
        cp16(dv, s_vT_h + gv);
        cp16(dv + 16, s_vT_h + gv + 8);
        cp_commit();
    };

    issue(0, stStart * 64);
    if (nTiles > 1) issue(1, (stStart + 1) * 64);

    for (int it = 0; it < nTiles; it++) {
        const int key_base = (stStart + it) * 64;
        if (it + 2 < nTiles) {
            issue((it + 2) & 3, (stStart + it + 2) * 64);
            cp_wait2();
        } else if (it + 1 < nTiles) {
            cp_wait1();
        } else {
            cp_wait0();
        }
        __syncthreads();

        const uint32_t stgK = sb + (it & 3) * F_STAGE;
        const uint32_t stgV = stgK + 9216;

        // ---- S = Q K^T ----
        float s[8][4];
        #pragma unroll
        for (int t = 0; t < 8; t++)
            #pragma unroll
            for (int i = 0; i < 4; i++) s[t][i] = 0.f;

        #pragma unroll
        for (int ks = 0; ks < 4; ks++) {
            uint32_t bf[8][2];
            #pragma unroll
            for (int p = 0; p < 4; p++) {
                uint32_t r[4];
                ldsm_x4(r, stgK + koff[p] + ks * 32);
                bf[p*2][0] = r[0]; bf[p*2][1] = r[1];
                bf[p*2+1][0] = r[2]; bf[p*2+1][1] = r[3];
            }
            #pragma unroll
            for (int tn = 0; tn < 8; tn++)
                mma_f16(s[tn], qh[ks], bf[tn]);
        }

        // ---- scale + bias + mask + exp (no max: scores bounded) ----
        const bool masked = (key_base + 63) > qrow0;
        #pragma unroll
        for (int tn = 0; tn < 8; tn++) {
            int key = key_base + tn * 8 + fkc;
            float2 dd = *(const float2*)(delta + b * SEQ + key);
            float d0 = 0.125f * dd.x, d1 = 0.125f * dd.y;
            s[tn][0] = fmaf(s[tn][0], sct, d0);
            s[tn][1] = fmaf(s[tn][1], sct, d1);
            s[tn][2] = fmaf(s[tn][2], sct, d0);
            s[tn][3] = fmaf(s[tn][3], sct, d1);
            if (masked) {
                if (key     > rA) s[tn][0] = -1e30f;
                if (key + 1 > rA) s[tn][1] = -1e30f;
                if (key     > rB) s[tn][2] = -1e30f;
                if (key + 1 > rB) s[tn][3] = -1e30f;
            }
            s[tn][0] = __expf(s[tn][0]);
            s[tn][1] = __expf(s[tn][1]);
            s[tn][2] = __expf(s[tn][2]);
            s[tn][3] = __expf(s[tn][3]);
        }

        // ---- O += P V;  l += P @ ones (tensor core) ----
        #pragma unroll
        for (int kc = 0; kc < 4; kc++) {
            uint32_t ah[4];
            ah[0] = hpack2(s[2*kc][0],   s[2*kc][1]);
            ah[1] = hpack2(s[2*kc][2],   s[2*kc][3]);
            ah[2] = hpack2(s[2*kc+1][0], s[2*kc+1][1]);
            ah[3] = hpack2(s[2*kc+1][2], s[2*kc+1][3]);
            mma_f16(lacc, ah, onesB);
            uint32_t vf[8][2];
            #pragma unroll
            for (int p = 0; p < 4; p++) {
                uint32_t r[4];
                ldsm_x4(r, stgV + koff[p] + kc * 32);
                vf[p*2][0] = r[0]; vf[p*2][1] = r[1];
                vf[p*2+1][0] = r[2]; vf[p*2+1][1] = r[3];
            }
            #pragma unroll
            for (int tn2 = 0; tn2 < 8; tn2++)
                mma_f16(oacc[tn2], ah, vf[tn2]);
        }
        // no trailing sync (4-stage ring, write-ahead 2)
    }

    // ---- write partials (unnormalized O + l) ----
    float* po = z ? g_po1 : g_po0;
    float* gl = z ? g_l1 : g_l0;
    #pragma unroll
    for (int tn2 = 0; tn2 < 8; tn2++) {
        int col = h * EDIM + tn2 * 8 + fkc;
        *(float2*)&po[(size_t)(b * SEQ + rA) * D_MODEL + col] = make_float2(oacc[tn2][0], oacc[tn2][1]);
        *(float2*)&po[(size_t)(b * SEQ + rB) * D_MODEL + col] = make_float2(oacc[tn2][2], oacc[tn2][3]);
    }
    if ((lane & 3) == 0) {
        gl[(size_t)bh * SEQ + rA] = lacc[0];
        gl[(size_t)bh * SEQ + rB] = lacc[2];
    }
}

// merge split-KV partials -> fp16 attn output (8 elems/thread, uint4 store)
__global__ __launch_bounds__(256) void merge_k()
{
    const int idx8 = (blockIdx.x * 256 + threadIdx.x) * 8;
    const int r = idx8 >> 9;
    const int d = idx8 & 511;
    const int bh = ((r >> 11) << 3) | (d >> 6);
    const int srow = r & (SEQ - 1);
    float l0 = g_l0[(size_t)bh * SEQ + srow];
    float l1 = g_l1[(size_t)bh * SEQ + srow];
    float inv = 1.0f / (l0 + l1);
    float4 p0a = *(float4*)&g_po0[idx8];
    float4 p0b = *(float4*)&g_po0[idx8 + 4];
    float4 p1a = *(float4*)&g_po1[idx8];
    float4 p1b = *(float4*)&g_po1[idx8 + 4];
    uint4 out;
    out.x = hpack2((p0a.x + p1a.x) * inv, (p0a.y + p1a.y) * inv);
    out.y = hpack2((p0a.z + p1a.z) * inv, (p0a.w + p1a.w) * inv);
    out.z = hpack2((p0b.x + p1b.x) * inv, (p0b.y + p1b.y) * inv);
    out.w = hpack2((p0b.z + p1b.z) * inv, (p0b.w + p1b.w) * inv);
    *(uint4*)&s_attn_h[idx8] = out;
}

// ---------------- LayerNorm: 2 rows per block, 256 threads ----------------
__global__ __launch_bounds__(256) void ln_k(
    const float* __restrict__ x, const float* __restrict__ g,
    const float* __restrict__ bb, float* __restrict__ y,
    uint16_t* __restrict__ yh)
{
    const int sub = threadIdx.x >> 7;
    const int tid = threadIdx.x & 127;
    const int row = blockIdx.x * 2 + sub;
    const float* p = x + (size_t)row * D_MODEL;
    float4 v = *(const float4*)(p + tid * 4);
    float s = v.x + v.y + v.z + v.w;
    __shared__ float sh[8];
    #pragma unroll
    for (int o = 16; o > 0; o >>= 1) s += __shfl_xor_sync(~0u, s, o);
    if ((threadIdx.x & 31) == 0) sh[threadIdx.x >> 5] = s;
    __syncthreads();
    const int base4 = sub * 4;
    s = sh[base4] + sh[base4+1] + sh[base4+2] + sh[base4+3];
    const float mean = s * (1.0f / (float)D_MODEL);
    float vs = (v.x - mean) * (v.x - mean) + (v.y - mean) * (v.y - mean)
             + (v.z - mean) * (v.z - mean) + (v.w - mean) * (v.w - mean);
    #pragma unroll
    for (int o = 16; o > 0; o >>= 1) vs += __shfl_xor_sync(~0u, vs, o);
    __syncthreads();
    if ((threadIdx.x & 31) == 0) sh[threadIdx.x >> 5] = vs;
    __syncthreads();
    vs = sh[base4] + sh[base4+1] + sh[base4+2] + sh[base4+3];
    const float rstd = rsqrtf(vs * (1.0f / (float)D_MODEL) + 1e-5f);
    const int col = tid * 4;
    const float4 gg = *(const float4*)(g + col);
    const float4 bbv = *(const float4*)(bb + col);
    float4 out;
    out.x = (v.x - mean) * rstd * gg.x + bbv.x;
    out.y = (v.y - mean) * rstd * gg.y + bbv.y;
    out.z = (v.z - mean) * rstd * gg.z + bbv.z;
    out.w = (v.w - mean) * rstd * gg.w + bbv.w;
    *(float4*)(y + (size_t)row * D_MODEL + col) = out;
    if (yh != nullptr) {
        size_t o = (size_t)row * D_MODEL + col;
        *(uint32_t*)&yh[o]     = hpack2(out.x, out.y);
        *(uint32_t*)&yh[o + 2] = hpack2(out.z, out.w);
    }
}

// ---------------- orchestration ----------------
extern "C" void kernel_launch(void* const* d_in, const int* in_sizes, int n_in,
                              void* d_out, int out_size)
{
    const float* x_in  = (const float*)d_in[0];
    const float* tau   = (const float*)d_in[1];
    const float* delta = (const float*)d_in[2];
    const float* Wq = (const float*)d_in[4];
    const float* bq = (const float*)d_in[5];
    const float* Wk = (const float*)d_in[6];
    const float* bk = (const float*)d_in[7];
    const float* Wv = (const float*)d_in[8];
    const float* bv = (const float*)d_in[9];
    const float* Wo = (const float*)d_in[10];
    const float* bo = (const float*)d_in[11];
    const float* W1 = (const float*)d_in[12];
    const float* b1 = (const float*)d_in[13];
    const float* W2 = (const float*)d_in[14];
    const float* b2 = (const float*)d_in[15];
    const float* ln1g = (const float*)d_in[16];
    const float* ln1b = (const float*)d_in[17];
    const float* ln2g = (const float*)d_in[18];
    const float* ln2b = (const float*)d_in[19];
    const float* lnfg = (const float*)d_in[20];
    const float* lnfb = (const float*)d_in[21];

    float *gx, *gxb, *go;
    cudaGetSymbolAddress((void**)&gx,  g_x);
    cudaGetSymbolAddress((void**)&gxb, g_xb);
    cudaGetSymbolAddress((void**)&go,  g_o);

    uint16_t *axh, *axbh, *ahh, *aath;
    cudaGetSymbolAddress((void**)&axh,  s_x_h);
    cudaGetSymbolAddress((void**)&axbh, s_xb_h);
    cudaGetSymbolAddress((void**)&ahh,  s_h_h);
    cudaGetSymbolAddress((void**)&aath, s_attn_h);

    uint16_t *wo_h, *w1_h, *w2_h;
    cudaGetSymbolAddress((void**)&wo_h, s_Wo_h);
    cudaGetSymbolAddress((void**)&w1_h, s_W1_h);
    cudaGetSymbolAddress((void**)&w2_h, s_W2_h);

    const int SM2 = 4 * (10240 + 2 * 2560);   // 61440

    cudaFuncSetAttribute(gemm_split2, cudaFuncAttributeMaxDynamicSharedMemorySize, SM2);
    cudaFuncSetAttribute(gemm_qkv,    cudaFuncAttributeMaxDynamicSharedMemorySize, SM2);
    cudaFuncSetAttribute(flash_split, cudaFuncAttributeMaxDynamicSharedMemorySize, F_SMEM);

    transp_split<<<dim3(64, 64, 13), 256>>>(Wq, Wk, Wv, Wo, W1, W2, x_in);

    const dim3 gQKV(D_MODEL / 64, ROWS / 128, 3);      // (8, 32, 3)
    const dim3 gProj64(D_MODEL / 64, ROWS / 128);      // (8, 32)
    const dim3 gFF1(D_FF / 64, ROWS / 128);            // (32, 32)
    const dim3 gFlash(2 * SEQ / 128, BH);              // (32, 16)

    for (int l = 0; l < 2; l++) {
        const int wOff   = l * D_MODEL * D_MODEL;
        const int w1Off  = l * D_MODEL * D_FF;
        const size_t bOff  = (size_t)l * D_MODEL;
        const size_t b1Off = (size_t)l * D_FF;

        gemm_qkv<<<gQKV, 256, SM2>>>(bq + bOff, bk + bOff, bv + bOff, wOff);
        flash_split<<<gFlash, 256, F_SMEM>>>(tau, delta);
        merge_k<<<ROWS * D_MODEL / 2048, 256>>>();

        gemm_split2<<<gProj64, 256, SM2>>>(aath, wo_h + wOff,
                                           bo + bOff, gx, gx, nullptr,
                                           D_MODEL, D_MODEL, 1);
        ln_k<<<ROWS / 2, 256>>>(gx, ln1g + bOff, ln1b + bOff, gxb, axbh);

        gemm_split2<<<gFF1, 256, SM2>>>(axbh, w1_h + w1Off,
                                        b1 + b1Off, nullptr, nullptr, ahh,
                                        D_FF, D_MODEL, 2);
        gemm_split2<<<gProj64, 256, SM2>>>(ahh, w2_h + w1Off,
                                           b2 + bOff, gxb, go, nullptr,
                                           D_MODEL, D_FF, 1);
        ln_k<<<ROWS / 2, 256>>>(go, ln2g + bOff, ln2b + bOff, gx, axh);
    }
    ln_k<<<ROWS / 2, 256>>>(gx, lnfg, lnfb, (float*)d_out, nullptr);
}

// round 17
// speedup vs baseline: 1.0673x; 1.0673x over previous
#include <cuda_runtime.h>
#include <cuda_fp16.h>
#include <math.h>
#include <stdint.h>

#define D_MODEL 512
#define D_FF 2048
#define BATCH 2
#define SEQ 2048
#define NHEADS 8
#define EDIM 64
#define ROWS (BATCH*SEQ)
#define BH (BATCH*NHEADS)
#define GELU_CF 0.7978845608028654f
#define WSZ  (2*D_MODEL*D_MODEL)
#define W1SZ (2*D_MODEL*D_FF)

// ---------------- f32 scratch ----------------
__device__ float g_x[ROWS*D_MODEL];
__device__ float g_xb[ROWS*D_MODEL];
__device__ float g_o[ROWS*D_MODEL];
__device__ float g_po0[ROWS*D_MODEL];
__device__ float g_po1[ROWS*D_MODEL];
__device__ float g_l0[BH*SEQ];
__device__ float g_l1[BH*SEQ];

// ---------------- fp16 TRANSPOSED weights ([layer][N][K]) ----------------
__device__ uint16_t s_Wq_h[WSZ];
__device__ uint16_t s_Wk_h[WSZ];
__device__ uint16_t s_Wv_h[WSZ];
__device__ uint16_t s_Wo_h[WSZ];
__device__ uint16_t s_W1_h[W1SZ];
__device__ uint16_t s_W2_h[W1SZ];

// ---------------- fp16 activations ----------------
__device__ uint16_t s_x_h[ROWS*D_MODEL];
__device__ uint16_t s_xb_h[ROWS*D_MODEL];
__device__ uint16_t s_q_h[ROWS*D_MODEL];
__device__ uint16_t s_k_h[ROWS*D_MODEL];
__device__ uint16_t s_vT_h[ROWS*D_MODEL];   // [bh][e][tok]
__device__ uint16_t s_attn_h[ROWS*D_MODEL];
__device__ uint16_t s_h_h[ROWS*D_FF];

// =======================================================================
// helpers
// =======================================================================
__device__ __forceinline__ uint32_t hpack2(float x0, float x1) {
    __half2 hh = __floats2half2_rn(x0, x1);
    return *reinterpret_cast<uint32_t*>(&hh);
}

__device__ __forceinline__ void mma_f16(float* c, const uint32_t* a, const uint32_t* b) {
    asm volatile(
        "mma.sync.aligned.m16n8k16.row.col.f32.f16.f16.f32 "
        "{%0,%1,%2,%3}, {%4,%5,%6,%7}, {%8,%9}, {%0,%1,%2,%3};"
        : "+f"(c[0]), "+f"(c[1]), "+f"(c[2]), "+f"(c[3])
        : "r"(a[0]), "r"(a[1]), "r"(a[2]), "r"(a[3]), "r"(b[0]), "r"(b[1]));
}

__device__ __forceinline__ void ldsm_x4(uint32_t* r, uint32_t addr) {
    asm volatile("ldmatrix.sync.aligned.m8n8.x4.shared.b16 {%0,%1,%2,%3}, [%4];"
        : "=r"(r[0]), "=r"(r[1]), "=r"(r[2]), "=r"(r[3]) : "r"(addr));
}

__device__ __forceinline__ uint32_t smem_u32(const void* p) {
    uint32_t a;
    asm("{ .reg .u64 t; cvta.to.shared.u64 t, %1; cvt.u32.u64 %0, t; }"
        : "=r"(a) : "l"(p));
    return a;
}

__device__ __forceinline__ void cp16(uint32_t dst, const void* src) {
    asm volatile("cp.async.cg.shared.global [%0], [%1], 16;\n" :: "r"(dst), "l"(src));
}
__device__ __forceinline__ void cp_commit() {
    asm volatile("cp.async.commit_group;\n" ::: "memory");
}
__device__ __forceinline__ void cp_wait2() {
    asm volatile("cp.async.wait_group 2;\n" ::: "memory");
}
__device__ __forceinline__ void cp_wait1() {
    asm volatile("cp.async.wait_group 1;\n" ::: "memory");
}
__device__ __forceinline__ void cp_wait0() {
    asm volatile("cp.async.wait_group 0;\n" ::: "memory");
}

// =======================================================================
// prologue: exact-size 1D grid (8192 blocks), no early-return waste.
// u in [0,2048): 512x512 weights (8 mats x 256 tiles)
// u in [2048,4096): W1 (2 layers x 1024 tiles)
// u in [4096,6144): W2 (2 layers x 1024 tiles)
// u in [6144,8192): input split (2048 blocks)
// =======================================================================
__global__ __launch_bounds__(256) void transp_split(
    const float* __restrict__ Wq, const float* __restrict__ Wk,
    const float* __restrict__ Wv, const float* __restrict__ Wo,
    const float* __restrict__ W1, const float* __restrict__ W2,
    const float* __restrict__ x)
{
    const int u = blockIdx.x;
    if (u >= 6144) {
        int bid = u - 6144;
        int idx = (bid * 256 + threadIdx.x) * 4;
        float4 v = *(const float4*)(x + idx);
        *(float4*)(g_x + idx) = v;
        *(uint32_t*)&s_x_h[idx]     = hpack2(v.x, v.y);
        *(uint32_t*)&s_x_h[idx + 2] = hpack2(v.z, v.w);
        return;
    }
    const float* src; uint16_t* dh; int K, N, layer, k0, n0;
    if (u < 2048) {
        int mat = u >> 8, r = u & 255;
        int w = mat >> 1; layer = mat & 1;
        K = 512; N = 512;
        k0 = (r & 15) * 32; n0 = (r >> 4) * 32;
        switch (w) {
            case 0: src = Wq; dh = s_Wq_h; break;
            case 1: src = Wk; dh = s_Wk_h; break;
            case 2: src = Wv; dh = s_Wv_h; break;
            default: src = Wo; dh = s_Wo_h; break;
        }
    } else if (u < 4096) {
        int v = u - 2048;
        layer = v >> 10; int r = v & 1023;
        src = W1; dh = s_W1_h; K = 512; N = 2048;
        k0 = (r & 15) * 32; n0 = (r >> 4) * 32;
    } else {
        int v = u - 4096;
        layer = v >> 10; int r = v & 1023;
        src = W2; dh = s_W2_h; K = 2048; N = 512;
        k0 = (r & 63) * 32; n0 = (r >> 6) * 32;
    }
    src += (size_t)layer * K * N;
    dh  += (size_t)layer * K * N;

    __shared__ float t[32][33];
    const int tid = threadIdx.x;
    const int tx = tid & 31, ty = tid >> 5;
    #pragma unroll
    for (int i = 0; i < 4; i++) {
        int k = ty + i * 8;
        t[k][tx] = src[(size_t)(k0 + k) * N + n0 + tx];
    }
    __syncthreads();
    const int n = tid >> 3, kq = tid & 7;
    float a0 = t[kq*4+0][n], a1 = t[kq*4+1][n], a2 = t[kq*4+2][n], a3 = t[kq*4+3][n];
    size_t o = (size_t)(n0 + n) * K + k0 + kq * 4;
    *(uint32_t*)&dh[o]     = hpack2(a0, a1);
    *(uint32_t*)&dh[o + 2] = hpack2(a2, a3);
}

// =======================================================================
// GEMM: pure fp16, ldmatrix frags. A [M][K], B (transposed weights) [N][K].
// Block tile 128 x (TN*32). 256 thr. 4-stage cp.async pipeline, single sync.
// =======================================================================
#define A_PITCH 40

// epi: 0 = bias -> fp16 out; 1 = bias + add -> f32 out; 2 = bias + gelu -> fp16 out;
//      3 = bias -> transposed fp16 V out (s_vT_h), requires TN==2 & head-aligned bn
template<int TN>
__device__ __forceinline__ void gemm_body(
    const uint16_t* __restrict__ Ah, const uint16_t* __restrict__ Bh,
    const float* __restrict__ bias, const float* __restrict__ add,
    float* __restrict__ Cf, uint16_t* __restrict__ Ch,
    int N, int K, int epi, int bm, int bn, char* sm)
{
    constexpr int STAGE = 10240 + TN * 2560;
    constexpr int NP = TN / 2;
    const int tid = threadIdx.x;
    const int wid = tid >> 5;
    const int lane = tid & 31;
    const int wm = wid & 1;
    const int wn = wid >> 1;
    const int fr = lane >> 2;
    const int fkc = (lane & 3) * 2;
    const int mi = lane >> 3, ri = lane & 7;
    const uint32_t sb = smem_u32(sm);

    int aoff[4];
    #pragma unroll
    for (int tm = 0; tm < 4; tm++)
        aoff[tm] = ((wm * 64 + tm * 16 + (mi & 1) * 8 + ri) * A_PITCH + (mi >> 1) * 8) * 2;
    int boff[NP];
    #pragma unroll
    for (int p = 0; p < NP; p++)
        boff[p] = ((wn * (TN * 8) + (p * 2 + (mi >> 1)) * 8 + ri) * A_PITCH + (mi & 1) * 8) * 2;

    float acc[4][TN][4];
    #pragma unroll
    for (int tm = 0; tm < 4; tm++)
        #pragma unroll
        for (int tn = 0; tn < TN; tn++)
            #pragma unroll
            for (int i = 0; i < 4; i++) acc[tm][tn][i] = 0.f;

    const int nChunks = K >> 5;

    auto issue = [&](int st, int kt) {
        uint32_t base = sb + st * STAGE;
        #pragma unroll
        for (int t = 0; t < 2 + NP; t++) {
            int idx = tid + t * 256;
            if (idx < 512) {
                int row = idx >> 2, c4 = idx & 3;
                cp16(base + row * 80 + c4 * 16, Ah + (size_t)(bm + row) * K + kt + c4 * 8);
            } else {
                int j = idx - 512;
                int row = j >> 2, c4 = j & 3;
                cp16(base + 10240 + row * 80 + c4 * 16, Bh + (size_t)(bn + row) * K + kt + c4 * 8);
            }
        }
        cp_commit();
    };

    issue(0, 0);
    if (nChunks > 1) issue(1, 32);

    for (int chunk = 0; chunk < nChunks; chunk++) {
        if (chunk + 2 < nChunks) {
            issue((chunk + 2) & 3, (chunk + 2) << 5);
            cp_wait2();
        } else if (chunk + 1 < nChunks) {
            cp_wait1();
        } else {
            cp_wait0();
        }
        __syncthreads();

        const uint32_t stgA = sb + (chunk & 3) * STAGE;
        const uint32_t stgB = stgA + 10240;

        #pragma unroll
        for (int ks = 0; ks < 2; ks++) {
            const int K0b = ks * 32;
            uint32_t ah[4][4];
            #pragma unroll
            for (int tm = 0; tm < 4; tm++)
                ldsm_x4(ah[tm], stgA + aoff[tm] + K0b);
            uint32_t bhf[TN][2];
            #pragma unroll
            for (int p = 0; p < NP; p++) {
                uint32_t r[4];
                ldsm_x4(r, stgB + boff[p] + K0b);
                bhf[p*2][0] = r[0]; bhf[p*2][1] = r[1];
                bhf[p*2+1][0] = r[2]; bhf[p*2+1][1] = r[3];
            }
            #pragma unroll
            for (int tm = 0; tm < 4; tm++)
                #pragma unroll
                for (int tn = 0; tn < TN; tn++)
                    mma_f16(acc[tm][tn], ah[tm], bhf[tn]);
        }
        // no trailing sync: 4-stage ring + write-ahead-2 + skew<=1 is race-free
    }

    if (epi == 3) {
        __syncthreads();
        uint16_t (*stg)[66] = (uint16_t(*)[66])sm;
        #pragma unroll
        for (int tm = 0; tm < 4; tm++) {
            #pragma unroll
            for (int tn = 0; tn < TN; tn++) {
                int lcol = wn * (TN * 8) + tn * 8 + fkc;
                float b0 = bias[bn + lcol], b1 = bias[bn + lcol + 1];
                #pragma unroll
                for (int half = 0; half < 2; half++) {
                    int lrow = wm * 64 + tm * 16 + fr + half * 8;
                    float v0 = acc[tm][tn][half * 2 + 0] + b0;
                    float v1 = acc[tm][tn][half * 2 + 1] + b1;
                    *(uint32_t*)&stg[lrow][lcol] = hpack2(v0, v1);
                }
            }
        }
        __syncthreads();
        const int bh = (bm >> 11) * NHEADS + (bn >> 6);
        const int tok0 = bm & (SEQ - 1);
        #pragma unroll
        for (int i = tid; i < 64 * 64; i += 256) {
            int e = i >> 6, t2 = (i & 63) * 2;
            uint32_t v = (uint32_t)stg[t2][e] | ((uint32_t)stg[t2 + 1][e] << 16);
            *(uint32_t*)&s_vT_h[((size_t)bh * EDIM + e) * SEQ + tok0 + t2] = v;
        }
        return;
    }

    #pragma unroll
    for (int tm = 0; tm < 4; tm++) {
        #pragma unroll
        for (int tn = 0; tn < TN; tn++) {
            int row0 = bm + wm * 64 + tm * 16 + fr;
            int col = bn + wn * (TN * 8) + tn * 8 + fkc;
            float b0 = bias[col], b1 = bias[col + 1];
            #pragma unroll
            for (int half = 0; half < 2; half++) {
                int row = row0 + half * 8;
                float v0 = acc[tm][tn][half * 2 + 0] + b0;
                float v1 = acc[tm][tn][half * 2 + 1] + b1;
                if (epi == 1) {
                    const float* ap = add + (size_t)row * N + col;
                    v0 += ap[0]; v1 += ap[1];
                    *(float2*)(Cf + (size_t)row * N + col) = make_float2(v0, v1);
                } else {
                    if (epi == 2) {
                        float u = v0;
                        v0 = 0.5f * u * (1.0f + tanhf(GELU_CF * (u + 0.044715f * u * u * u)));
                        u = v1;
                        v1 = 0.5f * u * (1.0f + tanhf(GELU_CF * (u + 0.044715f * u * u * u)));
                    }
                    *(uint32_t*)&Ch[(size_t)row * N + col] = hpack2(v0, v1);
                }
            }
        }
    }
}

// TN=4 path: 2 CTAs/SM (best for wide-N FF1)
template<int TN>
__global__ __launch_bounds__(256, 2) void gemm_split_t(
    const uint16_t* __restrict__ Ah, const uint16_t* __restrict__ Bh,
    const float* __restrict__ bias, const float* __restrict__ add,
    float* __restrict__ Cf, uint16_t* __restrict__ Ch,
    int N, int K, int epi)
{
    extern __shared__ char sm[];
    gemm_body<TN>(Ah, Bh, bias, add, Cf, Ch, N, K, epi,
                  blockIdx.y * 128, blockIdx.x * (TN * 32), sm);
}

// TN=2 path: 3 CTAs/SM (best for N=512 GEMMs)
__global__ __launch_bounds__(256, 3) void gemm_split2(
    const uint16_t* __restrict__ Ah, const uint16_t* __restrict__ Bh,
    const float* __restrict__ bias, const float* __restrict__ add,
    float* __restrict__ Cf, uint16_t* __restrict__ Ch,
    int N, int K, int epi)
{
    extern __shared__ char sm[];
    gemm_body<2>(Ah, Bh, bias, add, Cf, Ch, N, K, epi,
                 blockIdx.y * 128, blockIdx.x * 64, sm);
}

__global__ __launch_bounds__(256, 3) void gemm_qkv(
    const float* __restrict__ bq, const float* __restrict__ bk,
    const float* __restrict__ bv, int lw)
{
    extern __shared__ char sm[];
    const int z = blockIdx.z;
    if (z == 0) {
        gemm_body<2>(s_x_h, s_Wq_h + lw, bq, nullptr, nullptr, s_q_h,
                     D_MODEL, D_MODEL, 0, blockIdx.y * 128, blockIdx.x * 64, sm);
    } else if (z == 1) {
        gemm_body<2>(s_x_h, s_Wk_h + lw, bk, nullptr, nullptr, s_k_h,
                     D_MODEL, D_MODEL, 0, blockIdx.y * 128, blockIdx.x * 64, sm);
    } else {
        gemm_body<2>(s_x_h, s_Wv_h + lw, bv, nullptr, nullptr, nullptr,
                     D_MODEL, D_MODEL, 3, blockIdx.y * 128, blockIdx.x * 64, sm);
    }
}

// =======================================================================
// Flash attention, 2-way split-KV, pure fp16, ldmatrix frags.
// No-max softmax + tensor-core row sums. 4-stage cp.async, single sync/tile.
// =======================================================================
#define KP 72
#define F_STAGE 18432
#define F_SMEM (4*F_STAGE)

__global__ __launch_bounds__(256, 2) void flash_split(
    const float* __restrict__ tau, const float* __restrict__ delta)
{
    extern __shared__ char sm[];
    const uint32_t sb = smem_u32(sm);
    const int tid = threadIdx.x;
    const int wid = tid >> 5;
    const int lane = tid & 31;
    const int fr = lane >> 2;
    const int fkc = (lane & 3) * 2;
    const int mi = lane >> 3, ri = lane & 7;

    const int nLt = gridDim.x >> 1;
    const int lt = nLt - 1 - (blockIdx.x >> 1);
    const int z = blockIdx.x & 1;
    const int bh = blockIdx.y;
    const int b = bh >> 3, h = bh & 7;
    const int qrow0 = lt * 128;
    const int rA = qrow0 + wid * 16 + fr;
    const int rB = rA + 8;

    int koff[4];
    #pragma unroll
    for (int p = 0; p < 4; p++)
        koff[p] = (((p * 2 + (mi >> 1)) * 8 + ri) * KP + (mi & 1) * 8) * 2;

    uint32_t qh[4][4];
    #pragma unroll
    for (int ks = 0; ks < 4; ks++) {
        int e0 = ks * 16 + fkc;
        size_t oA = (size_t)(b * SEQ + rA) * D_MODEL + h * EDIM + e0;
        size_t oB = (size_t)(b * SEQ + rB) * D_MODEL + h * EDIM + e0;
        qh[ks][0] = *(const uint32_t*)&s_q_h[oA];
        qh[ks][1] = *(const uint32_t*)&s_q_h[oB];
        qh[ks][2] = *(const uint32_t*)&s_q_h[oA + 8];
        qh[ks][3] = *(const uint32_t*)&s_q_h[oB + 8];
    }

    float oacc[8][4];
    #pragma unroll
    for (int t = 0; t < 8; t++)
        #pragma unroll
        for (int i = 0; i < 4; i++) oacc[t][i] = 0.f;
    float lacc[4] = {0.f, 0.f, 0.f, 0.f};
    const uint32_t onesB[2] = {0x3C003C00u, 0x3C003C00u};
    const float sct = 0.125f * __ldg(&tau[b]);

    const int stStart = z * (lt + 1);
    const int nTiles = lt + 1;

    auto issue = [&](int stage, int key_base) {
        uint32_t base = sb + stage * F_STAGE;
        int row = tid >> 2, c4 = tid & 3;
        size_t gk = (size_t)(b * SEQ + key_base + row) * D_MODEL + h * EDIM + c4 * 16;
        uint32_t dk = base + row * 144 + c4 * 32;
        cp16(dk, s_k_h + gk);
        cp16(dk + 16, s_k_h + gk + 8);
        size_t gv = ((size_t)bh * EDIM + row) * SEQ + key_base + c4 * 16;
        uint32_t dv = base + 9216 + row * 144 + c4 * 32;
        cp16(dv, s_vT_h + gv);
        cp16(dv + 16, s_vT_h + gv + 8);
        cp_commit();
    };

    issue(0, stStart * 64);
    if (nTiles > 1) issue(1, (stStart + 1) * 64);

    for (int it = 0; it < nTiles; it++) {
        const int key_base = (stStart + it) * 64;
        if (it + 2 < nTiles) {
            issue((it + 2) & 3, (stStart + it + 2) * 64);
            cp_wait2();
        } else if (it + 1 < nTiles) {
            cp_wait1();
        } else {
            cp_wait0();
        }
        __syncthreads();

        const uint32_t stgK = sb + (it & 3) * F_STAGE;
        const uint32_t stgV = stgK + 9216;

        // ---- S = Q K^T ----
        float s[8][4];
        #pragma unroll
        for (int t = 0; t < 8; t++)
            #pragma unroll
            for (int i = 0; i < 4; i++) s[t][i] = 0.f;

        #pragma unroll
        for (int ks = 0; ks < 4; ks++) {
            uint32_t bf[8][2];
            #pragma unroll
            for (int p = 0; p < 4; p++) {
                uint32_t r[4];
                ldsm_x4(r, stgK + koff[p] + ks * 32);
                bf[p*2][0] = r[0]; bf[p*2][1] = r[1];
                bf[p*2+1][0] = r[2]; bf[p*2+1][1] = r[3];
            }
            #pragma unroll
            for (int tn = 0; tn < 8; tn++)
                mma_f16(s[tn], qh[ks], bf[tn]);
        }

        // ---- scale + bias + mask + exp (no max: scores bounded) ----
        const bool masked = (key_base + 63) > qrow0;
        #pragma unroll
        for (int tn = 0; tn < 8; tn++) {
            int key = key_base + tn * 8 + fkc;
            float2 dd = *(const float2*)(delta + b * SEQ + key);
            float d0 = 0.125f * dd.x, d1 = 0.125f * dd.y;
            s[tn][0] = fmaf(s[tn][0], sct, d0);
            s[tn][1] = fmaf(s[tn][1], sct, d1);
            s[tn][2] = fmaf(s[tn][2], sct, d0);
            s[tn][3] = fmaf(s[tn][3], sct, d1);
            if (masked) {
                if (key     > rA) s[tn][0] = -1e30f;
                if (key + 1 > rA) s[tn][1] = -1e30f;
                if (key     > rB) s[tn][2] = -1e30f;
                if (key + 1 > rB) s[tn][3] = -1e30f;
            }
            s[tn][0] = __expf(s[tn][0]);
            s[tn][1] = __expf(s[tn][1]);
            s[tn][2] = __expf(s[tn][2]);
            s[tn][3] = __expf(s[tn][3]);
        }

        // ---- O += P V;  l += P @ ones (tensor core) ----
        #pragma unroll
        for (int kc = 0; kc < 4; kc++) {
            uint32_t ah[4];
            ah[0] = hpack2(s[2*kc][0],   s[2*kc][1]);
            ah[1] = hpack2(s[2*kc][2],   s[2*kc][3]);
            ah[2] = hpack2(s[2*kc+1][0], s[2*kc+1][1]);
            ah[3] = hpack2(s[2*kc+1][2], s[2*kc+1][3]);
            mma_f16(lacc, ah, onesB);
            uint32_t vf[8][2];
            #pragma unroll
            for (int p = 0; p < 4; p++) {
                uint32_t r[4];
                ldsm_x4(r, stgV + koff[p] + kc * 32);
                vf[p*2][0] = r[0]; vf[p*2][1] = r[1];
                vf[p*2+1][0] = r[2]; vf[p*2+1][1] = r[3];
            }
            #pragma unroll
            for (int tn2 = 0; tn2 < 8; tn2++)
                mma_f16(oacc[tn2], ah, vf[tn2]);
        }
        // no trailing sync (4-stage ring, write-ahead 2)
    }

    // ---- write partials (unnormalized O + l) ----
    float* po = z ? g_po1 : g_po0;
    float* gl = z ? g_l1 : g_l0;
    #pragma unroll
    for (int tn2 = 0; tn2 < 8; tn2++) {
        int col = h * EDIM + tn2 * 8 + fkc;
        *(float2*)&po[(size_t)(b * SEQ + rA) * D_MODEL + col] = make_float2(oacc[tn2][0], oacc[tn2][1]);
        *(float2*)&po[(size_t)(b * SEQ + rB) * D_MODEL + col] = make_float2(oacc[tn2][2], oacc[tn2][3]);
    }
    if ((lane & 3) == 0) {
        gl[(size_t)bh * SEQ + rA] = lacc[0];
        gl[(size_t)bh * SEQ + rB] = lacc[2];
    }
}

// merge split-KV partials -> fp16 attn output (8 elems/thread, uint4 store)
__global__ __launch_bounds__(256) void merge_k()
{
    const int idx8 = (blockIdx.x * 256 + threadIdx.x) * 8;
    const int r = idx8 >> 9;
    const int d = idx8 & 511;
    const int bh = ((r >> 11) << 3) | (d >> 6);
    const int srow = r & (SEQ - 1);
    float l0 = g_l0[(size_t)bh * SEQ + srow];
    float l1 = g_l1[(size_t)bh * SEQ + srow];
    float inv = 1.0f / (l0 + l1);
    float4 p0a = *(float4*)&g_po0[idx8];
    float4 p0b = *(float4*)&g_po0[idx8 + 4];
    float4 p1a = *(float4*)&g_po1[idx8];
    float4 p1b = *(float4*)&g_po1[idx8 + 4];
    uint4 out;
    out.x = hpack2((p0a.x + p1a.x) * inv, (p0a.y + p1a.y) * inv);
    out.y = hpack2((p0a.z + p1a.z) * inv, (p0a.w + p1a.w) * inv);
    out.z = hpack2((p0b.x + p1b.x) * inv, (p0b.y + p1b.y) * inv);
    out.w = hpack2((p0b.z + p1b.z) * inv, (p0b.w + p1b.w) * inv);
    *(uint4*)&s_attn_h[idx8] = out;
}

// ---------------- LayerNorm: 2 rows per block, 256 threads ----------------
__global__ __launch_bounds__(256) void ln_k(
    const float* __restrict__ x, const float* __restrict__ g,
    const float* __restrict__ bb, float* __restrict__ y,
    uint16_t* __restrict__ yh)
{
    const int sub = threadIdx.x >> 7;
    const int tid = threadIdx.x & 127;
    const int row = blockIdx.x * 2 + sub;
    const float* p = x + (size_t)row * D_MODEL;
    float4 v = *(const float4*)(p + tid * 4);
    float s = v.x + v.y + v.z + v.w;
    __shared__ float sh[8];
    #pragma unroll
    for (int o = 16; o > 0; o >>= 1) s += __shfl_xor_sync(~0u, s, o);
    if ((threadIdx.x & 31) == 0) sh[threadIdx.x >> 5] = s;
    __syncthreads();
    const int base4 = sub * 4;
    s = sh[base4] + sh[base4+1] + sh[base4+2] + sh[base4+3];
    const float mean = s * (1.0f / (float)D_MODEL);
    float vs = (v.x - mean) * (v.x - mean) + (v.y - mean) * (v.y - mean)
             + (v.z - mean) * (v.z - mean) + (v.w - mean) * (v.w - mean);
    #pragma unroll
    for (int o = 16; o > 0; o >>= 1) vs += __shfl_xor_sync(~0u, vs, o);
    __syncthreads();
    if ((threadIdx.x & 31) == 0) sh[threadIdx.x >> 5] = vs;
    __syncthreads();
    vs = sh[base4] + sh[base4+1] + sh[base4+2] + sh[base4+3];
    const float rstd = rsqrtf(vs * (1.0f / (float)D_MODEL) + 1e-5f);
    const int col = tid * 4;
    const float4 gg = *(const float4*)(g + col);
    const float4 bbv = *(const float4*)(bb + col);
    float4 out;
    out.x = (v.x - mean) * rstd * gg.x + bbv.x;
    out.y = (v.y - mean) * rstd * gg.y + bbv.y;
    out.z = (v.z - mean) * rstd * gg.z + bbv.z;
    out.w = (v.w - mean) * rstd * gg.w + bbv.w;
    *(float4*)(y + (size_t)row * D_MODEL + col) = out;
    if (yh != nullptr) {
        size_t o = (size_t)row * D_MODEL + col;
        *(uint32_t*)&yh[o]     = hpack2(out.x, out.y);
        *(uint32_t*)&yh[o + 2] = hpack2(out.z, out.w);
    }
}

// ---------------- orchestration ----------------
extern "C" void kernel_launch(void* const* d_in, const int* in_sizes, int n_in,
                              void* d_out, int out_size)
{
    const float* x_in  = (const float*)d_in[0];
    const float* tau   = (const float*)d_in[1];
    const float* delta = (const float*)d_in[2];
    const float* Wq = (const float*)d_in[4];
    const float* bq = (const float*)d_in[5];
    const float* Wk = (const float*)d_in[6];
    const float* bk = (const float*)d_in[7];
    const float* Wv = (const float*)d_in[8];
    const float* bv = (const float*)d_in[9];
    const float* Wo = (const float*)d_in[10];
    const float* bo = (const float*)d_in[11];
    const float* W1 = (const float*)d_in[12];
    const float* b1 = (const float*)d_in[13];
    const float* W2 = (const float*)d_in[14];
    const float* b2 = (const float*)d_in[15];
    const float* ln1g = (const float*)d_in[16];
    const float* ln1b = (const float*)d_in[17];
    const float* ln2g = (const float*)d_in[18];
    const float* ln2b = (const float*)d_in[19];
    const float* lnfg = (const float*)d_in[20];
    const float* lnfb = (const float*)d_in[21];

    float *gx, *gxb, *go;
    cudaGetSymbolAddress((void**)&gx,  g_x);
    cudaGetSymbolAddress((void**)&gxb, g_xb);
    cudaGetSymbolAddress((void**)&go,  g_o);

    uint16_t *axh, *axbh, *ahh, *aath;
    cudaGetSymbolAddress((void**)&axh,  s_x_h);
    cudaGetSymbolAddress((void**)&axbh, s_xb_h);
    cudaGetSymbolAddress((void**)&ahh,  s_h_h);
    cudaGetSymbolAddress((void**)&aath, s_attn_h);

    uint16_t *wo_h, *w1_h, *w2_h;
    cudaGetSymbolAddress((void**)&wo_h, s_Wo_h);
    cudaGetSymbolAddress((void**)&w1_h, s_W1_h);
    cudaGetSymbolAddress((void**)&w2_h, s_W2_h);

    const int SM4 = 4 * (10240 + 4 * 2560);   // 81920
    const int SM2 = 4 * (10240 + 2 * 2560);   // 61440

    cudaFuncSetAttribute(gemm_split_t<4>, cudaFuncAttributeMaxDynamicSharedMemorySize, SM4);
    cudaFuncSetAttribute(gemm_split2,     cudaFuncAttributeMaxDynamicSharedMemorySize, SM2);
    cudaFuncSetAttribute(gemm_qkv,        cudaFuncAttributeMaxDynamicSharedMemorySize, SM2);
    cudaFuncSetAttribute(flash_split,     cudaFuncAttributeMaxDynamicSharedMemorySize, F_SMEM);

    transp_split<<<8192, 256>>>(Wq, Wk, Wv, Wo, W1, W2, x_in);

    const dim3 gQKV(D_MODEL / 64, ROWS / 128, 3);      // (8, 32, 3)
    const dim3 gProj64(D_MODEL / 64, ROWS / 128);      // (8, 32)
    const dim3 gFF1(D_FF / 128, ROWS / 128);           // (16, 32)
    const dim3 gFlash(2 * SEQ / 128, BH);              // (32, 16)

    for (int l = 0; l < 2; l++) {
        const int wOff   = l * D_MODEL * D_MODEL;
        const int w1Off  = l * D_MODEL * D_FF;
        const size_t bOff  = (size_t)l * D_MODEL;
        const size_t b1Off = (size_t)l * D_FF;

        gemm_qkv<<<gQKV, 256, SM2>>>(bq + bOff, bk + bOff, bv + bOff, wOff);
        flash_split<<<gFlash, 256, F_SMEM>>>(tau, delta);
        merge_k<<<ROWS * D_MODEL / 2048, 256>>>();

        gemm_split2<<<gProj64, 256, SM2>>>(aath, wo_h + wOff,
                                           bo + bOff, gx, gx, nullptr,
                                           D_MODEL, D_MODEL, 1);
        ln_k<<<ROWS / 2, 256>>>(gx, ln1g + bOff, ln1b + bOff, gxb, axbh);

        gemm_split_t<4><<<gFF1, 256, SM4>>>(axbh, w1_h + w1Off,
                                            b1 + b1Off, nullptr, nullptr, ahh,
                                            D_FF, D_MODEL, 2);
        gemm_split2<<<gProj64, 256, SM2>>>(ahh, w2_h + w1Off,
                                           b2 + bOff, gxb, go, nullptr,
                                           D_MODEL, D_FF, 1);
        ln_k<<<ROWS / 2, 256>>>(go, ln2g + bOff, ln2b + bOff, gx, axh);
    }
    ln_k<<<ROWS / 2, 256>>>(gx, lnfg, lnfb, (float*)d_out, nullptr);
}